// round 2
// baseline (speedup 1.0000x reference)
#include <cuda_runtime.h>
#include <cuda_bf16.h>
#include <cstdint>

// Problem constants
#define BB 512
#define TT 128
#define CC 512
#define HH 8
#define LL 6
#define VV 13
#define DD 64
#define MM (BB*TT)          // 65536 rows in the token stream

// ---------------------------------------------------------------------------
// Scratch: 6 buffers of [M, C] fp32 = 6 * 128 MiB (static __device__, no alloc)
// ---------------------------------------------------------------------------
#define BUF_ELEMS ((size_t)MM * CC)
__device__ float g_scratch[6 * BUF_ELEMS];

// ---------------------------------------------------------------------------
// Embedding: x[b,t,:] = wte[tok[b,t],:] + wpe[t,:]
// grid = M blocks, 128 threads, one float4 per thread
// ---------------------------------------------------------------------------
__global__ void embed_kernel(const int* __restrict__ tok,
                             const float* __restrict__ wte,
                             const float* __restrict__ wpe,
                             float* __restrict__ x) {
    int row = blockIdx.x;
    int tid = threadIdx.x;                 // 0..127 (float4 index into 512 floats)
    int tkn = tok[row];
    int t = row & (TT - 1);                // row = b*T + t
    float4 a = ((const float4*)(wte + (size_t)tkn * CC))[tid];
    float4 p = ((const float4*)(wpe + (size_t)t * CC))[tid];
    float4 o;
    o.x = a.x + p.x; o.y = a.y + p.y; o.z = a.z + p.z; o.w = a.w + p.w;
    ((float4*)(x + (size_t)row * CC))[tid] = o;
}

// ---------------------------------------------------------------------------
// SGEMM: out[M,512] = A[M,512] @ W[512,512] + bias (+ residual)
// BM=BN=128, BK=16, 256 threads, 8x8 per thread (4+4 rake layout)
// ---------------------------------------------------------------------------
__global__ __launch_bounds__(256)
void sgemm_kernel(const float* __restrict__ A, const float* __restrict__ W,
                  const float* __restrict__ bias, const float* __restrict__ res,
                  float* __restrict__ out) {
    const int K = CC, N = CC;
    __shared__ float As[16][128];
    __shared__ float Bs[16][128];

    int bx = blockIdx.x;                   // n-block (0..3)
    int by = blockIdx.y;                   // m-block (0..511)
    int tid = threadIdx.x;
    int tx = tid & 15;
    int ty = tid >> 4;

    const float* Ab = A + (size_t)by * 128 * K;
    const float* Wb = W + bx * 128;

    float acc[8][8];
    #pragma unroll
    for (int i = 0; i < 8; i++)
        #pragma unroll
        for (int j = 0; j < 8; j++) acc[i][j] = 0.f;

    for (int k0 = 0; k0 < K; k0 += 16) {
        // A tile: 128 rows x 16 k, stored transposed As[k][row]
        #pragma unroll
        for (int s = 0; s < 2; s++) {
            int slot = tid + s * 256;      // 512 float4 slots
            int row = slot >> 2, kc = slot & 3;
            float4 v = *(const float4*)(Ab + (size_t)row * K + k0 + kc * 4);
            As[kc * 4 + 0][row] = v.x;
            As[kc * 4 + 1][row] = v.y;
            As[kc * 4 + 2][row] = v.z;
            As[kc * 4 + 3][row] = v.w;
        }
        // W tile: 16 k x 128 n
        #pragma unroll
        for (int s = 0; s < 2; s++) {
            int slot = tid + s * 256;
            int k = slot >> 5, n4 = slot & 31;
            *(float4*)(&Bs[k][n4 * 4]) = *(const float4*)(Wb + (size_t)(k0 + k) * N + n4 * 4);
        }
        __syncthreads();

        #pragma unroll
        for (int k = 0; k < 16; k++) {
            float4 a0 = *(const float4*)(&As[k][ty * 4]);
            float4 a1 = *(const float4*)(&As[k][64 + ty * 4]);
            float4 b0 = *(const float4*)(&Bs[k][tx * 4]);
            float4 b1 = *(const float4*)(&Bs[k][64 + tx * 4]);
            float ar[8] = {a0.x, a0.y, a0.z, a0.w, a1.x, a1.y, a1.z, a1.w};
            float br[8] = {b0.x, b0.y, b0.z, b0.w, b1.x, b1.y, b1.z, b1.w};
            #pragma unroll
            for (int i = 0; i < 8; i++)
                #pragma unroll
                for (int j = 0; j < 8; j++)
                    acc[i][j] += ar[i] * br[j];
        }
        __syncthreads();
    }

    // Epilogue: bias (+ residual), float4 stores
    int c0 = bx * 128 + tx * 4;
    int c1 = c0 + 64;
    float4 bias0 = *(const float4*)(bias + c0);
    float4 bias1 = *(const float4*)(bias + c1);
    #pragma unroll
    for (int i = 0; i < 8; i++) {
        int r = by * 128 + ((i < 4) ? (ty * 4 + i) : (64 + ty * 4 + i - 4));
        float4 o0, o1;
        o0.x = acc[i][0] + bias0.x; o0.y = acc[i][1] + bias0.y;
        o0.z = acc[i][2] + bias0.z; o0.w = acc[i][3] + bias0.w;
        o1.x = acc[i][4] + bias1.x; o1.y = acc[i][5] + bias1.y;
        o1.z = acc[i][6] + bias1.z; o1.w = acc[i][7] + bias1.w;
        if (res) {
            float4 r0 = *(const float4*)(res + (size_t)r * N + c0);
            float4 r1 = *(const float4*)(res + (size_t)r * N + c1);
            o0.x += r0.x; o0.y += r0.y; o0.z += r0.z; o0.w += r0.w;
            o1.x += r1.x; o1.y += r1.y; o1.z += r1.z; o1.w += r1.w;
        }
        *(float4*)(out + (size_t)r * N + c0) = o0;
        *(float4*)(out + (size_t)r * N + c1) = o1;
    }
}

// ---------------------------------------------------------------------------
// Per-position head attention: att[h,g] = softmax_g(q[h,:].k[g,:] / sqrt(D))
// hid[h,:] = att[h,:] @ v     (one block of 64 threads per (b,t) position)
// ---------------------------------------------------------------------------
__global__ void attn_kernel(const float* __restrict__ q,
                            const float* __restrict__ k,
                            const float* __restrict__ v,
                            float* __restrict__ out) {
    int r = blockIdx.x;
    int t = threadIdx.x;                    // 0..63
    __shared__ float qs[512], ks[512], vs[512], att_s[64];

    const float4* qp = (const float4*)(q + (size_t)r * CC);
    const float4* kp = (const float4*)(k + (size_t)r * CC);
    const float4* vp = (const float4*)(v + (size_t)r * CC);
    #pragma unroll
    for (int i = t; i < 128; i += 64) {
        ((float4*)qs)[i] = qp[i];
        ((float4*)ks)[i] = kp[i];
        ((float4*)vs)[i] = vp[i];
    }
    __syncthreads();

    int h = t >> 3, g = t & 7;
    float s = 0.f;
    #pragma unroll
    for (int d = 0; d < DD; d++) s += qs[h * DD + d] * ks[g * DD + d];
    s *= 0.125f;                            // 1/sqrt(64)

    // softmax over g (groups of 8, intra-warp)
    float m = s;
    #pragma unroll
    for (int o = 1; o < 8; o <<= 1) m = fmaxf(m, __shfl_xor_sync(0xffffffffu, m, o, 8));
    float e = expf(s - m);
    float sum = e;
    #pragma unroll
    for (int o = 1; o < 8; o <<= 1) sum += __shfl_xor_sync(0xffffffffu, sum, o, 8);
    att_s[t] = e / sum;
    __syncthreads();

    // hid[h][d]: thread (h, j=t&7) computes d = j*8 .. j*8+7
    int j = t & 7;
    float accv[8] = {0.f, 0.f, 0.f, 0.f, 0.f, 0.f, 0.f, 0.f};
    #pragma unroll
    for (int g2 = 0; g2 < 8; g2++) {
        float a = att_s[h * 8 + g2];
        #pragma unroll
        for (int jj = 0; jj < 8; jj++)
            accv[jj] += a * vs[g2 * DD + j * 8 + jj];
    }
    float* op = out + (size_t)r * CC + h * DD + j * 8;
    #pragma unroll
    for (int jj = 0; jj < 8; jj++) op[jj] = accv[jj];
}

// ---------------------------------------------------------------------------
// LayerNorm (warp per row): xo = (y - mean)/sqrt(var + 1e-5) * g + b
// ---------------------------------------------------------------------------
__global__ void ln_kernel(const float* __restrict__ y, const float* __restrict__ g,
                          const float* __restrict__ b, float* __restrict__ xo) {
    int warp = threadIdx.x >> 5;
    int lane = threadIdx.x & 31;
    size_t row = (size_t)blockIdx.x * 8 + warp;

    const float4* yp = (const float4*)(y + row * CC);
    float4 v[4];
    float s = 0.f, s2 = 0.f;
    #pragma unroll
    for (int i = 0; i < 4; i++) {
        v[i] = yp[lane + 32 * i];
        s  += v[i].x + v[i].y + v[i].z + v[i].w;
        s2 += v[i].x * v[i].x + v[i].y * v[i].y + v[i].z * v[i].z + v[i].w * v[i].w;
    }
    #pragma unroll
    for (int o = 16; o; o >>= 1) {
        s  += __shfl_xor_sync(0xffffffffu, s, o);
        s2 += __shfl_xor_sync(0xffffffffu, s2, o);
    }
    float mean = s * (1.f / 512.f);
    float var = s2 * (1.f / 512.f) - mean * mean;
    float rstd = rsqrtf(var + 1e-5f);

    float4* xp = (float4*)(xo + row * CC);
    const float4* gp = (const float4*)g;
    const float4* bp = (const float4*)b;
    #pragma unroll
    for (int i = 0; i < 4; i++) {
        float4 gg = gp[lane + 32 * i], bb = bp[lane + 32 * i], o;
        o.x = (v[i].x - mean) * rstd * gg.x + bb.x;
        o.y = (v[i].y - mean) * rstd * gg.y + bb.y;
        o.z = (v[i].z - mean) * rstd * gg.z + bb.z;
        o.w = (v[i].w - mean) * rstd * gg.w + bb.w;
        xp[lane + 32 * i] = o;
    }
}

// ---------------------------------------------------------------------------
// LM head (warp per row): logits[row, v] = x[row,:] @ W_lm[:, v] + b_lm[v]
// ---------------------------------------------------------------------------
__global__ void lmhead_kernel(const float* __restrict__ x, const float* __restrict__ Wlm,
                              const float* __restrict__ blm, float* __restrict__ logits) {
    int warp = threadIdx.x >> 5;
    int lane = threadIdx.x & 31;
    size_t row = (size_t)blockIdx.x * 8 + warp;

    float p[VV];
    #pragma unroll
    for (int vv = 0; vv < VV; vv++) p[vv] = 0.f;

    const float* xr = x + row * CC;
    for (int kk = lane; kk < CC; kk += 32) {
        float xv = xr[kk];
        const float* wrow = Wlm + (size_t)kk * VV;
        #pragma unroll
        for (int vv = 0; vv < VV; vv++) p[vv] += xv * wrow[vv];
    }
    #pragma unroll
    for (int vv = 0; vv < VV; vv++)
        #pragma unroll
        for (int o = 16; o; o >>= 1) p[vv] += __shfl_xor_sync(0xffffffffu, p[vv], o);

    if (lane == 0) {
        float* lp = logits + row * VV;
        #pragma unroll
        for (int vv = 0; vv < VV; vv++) lp[vv] = p[vv] + blm[vv];
    }
}

// ---------------------------------------------------------------------------
// Loss: -mean_b log_softmax(logits[b, T-1, :])[label[b]]
// ---------------------------------------------------------------------------
__global__ void loss_kernel(const float* __restrict__ logits, const int* __restrict__ label,
                            float* __restrict__ out_loss) {
    __shared__ float sdata[512];
    int b = threadIdx.x;                   // 512 threads
    const float* lg = logits + ((size_t)b * TT + (TT - 1)) * VV;
    float m = lg[0];
    #pragma unroll
    for (int vv = 1; vv < VV; vv++) m = fmaxf(m, lg[vv]);
    float s = 0.f;
    #pragma unroll
    for (int vv = 0; vv < VV; vv++) s += expf(lg[vv] - m);
    float lse = m + logf(s);
    sdata[b] = -(lg[label[b]] - lse);
    __syncthreads();
    for (int st = 256; st; st >>= 1) {
        if (b < st) sdata[b] += sdata[b + st];
        __syncthreads();
    }
    if (b == 0) *out_loss = sdata[0] * (1.f / BB);
}

// ---------------------------------------------------------------------------
// Host driver
// ---------------------------------------------------------------------------
extern "C" void kernel_launch(void* const* d_in, const int* in_sizes, int n_in,
                              void* d_out, int out_size) {
    const int*   tok   = (const int*)d_in[0];
    const int*   label = (const int*)d_in[1];
    const float* wte   = (const float*)d_in[2];
    const float* wpe   = (const float*)d_in[3];
    const float* Wq    = (const float*)d_in[4];
    const float* bq    = (const float*)d_in[5];
    const float* Wk    = (const float*)d_in[6];
    const float* bk    = (const float*)d_in[7];
    const float* Wv    = (const float*)d_in[8];
    const float* bv    = (const float*)d_in[9];
    const float* Wo    = (const float*)d_in[10];
    const float* bo    = (const float*)d_in[11];
    const float* ln_g  = (const float*)d_in[12];
    const float* ln_b  = (const float*)d_in[13];
    const float* Wlm   = (const float*)d_in[14];
    const float* blm   = (const float*)d_in[15];
    float* out = (float*)d_out;

    float* base = nullptr;
    cudaGetSymbolAddress((void**)&base, g_scratch);
    float* x   = base + 0 * BUF_ELEMS;
    float* q   = base + 1 * BUF_ELEMS;
    float* k   = base + 2 * BUF_ELEMS;
    float* v   = base + 3 * BUF_ELEMS;
    float* hid = base + 4 * BUF_ELEMS;
    float* y   = base + 5 * BUF_ELEMS;

    dim3 gemm_grid(4, MM / 128);

    embed_kernel<<<MM, 128>>>(tok, wte, wpe, x);

    for (int l = 0; l < LL; l++) {
        const size_t wOff = (size_t)l * CC * CC;
        const size_t bOff = (size_t)l * CC;
        sgemm_kernel<<<gemm_grid, 256>>>(x, Wq + wOff, bq + bOff, nullptr, q);
        sgemm_kernel<<<gemm_grid, 256>>>(x, Wk + wOff, bk + bOff, nullptr, k);
        sgemm_kernel<<<gemm_grid, 256>>>(x, Wv + wOff, bv + bOff, nullptr, v);
        attn_kernel<<<MM, 64>>>(q, k, v, hid);
        sgemm_kernel<<<gemm_grid, 256>>>(hid, Wo + wOff, bo + bOff, x, y);
        ln_kernel<<<MM / 8, 256>>>(y, ln_g + bOff, ln_b + bOff, x);
    }

    lmhead_kernel<<<MM / 8, 256>>>(x, Wlm, blm, out);

    if (out_size >= MM * VV + 1)
        loss_kernel<<<1, 512>>>(out, label, out + (MM * VV));
}

// round 4
// speedup vs baseline: 2.3585x; 2.3585x over previous
#include <cuda_runtime.h>
#include <cuda_bf16.h>
#include <cstdint>

#define BB 512
#define TT 128
#define CC 512
#define HH 8
#define LL 6
#define VV 13
#define DD 64
#define MM (BB*TT)

// ---------------- scratch arena (static, no allocation) ----------------
#define OFF_X    ((size_t)0)
#define SZ_X     ((size_t)MM*CC*4)
#define OFF_QKV  (OFF_X + SZ_X)
#define SZ_QKV   ((size_t)MM*1536*4)
#define OFF_Y    (OFF_QKV + SZ_QKV)
#define OFF_XH   (OFF_Y + SZ_X)
#define SZ_BH    ((size_t)MM*CC*2)
#define OFF_XL   (OFF_XH + SZ_BH)
#define OFF_HHI  (OFF_XL + SZ_BH)
#define OFF_HLO  (OFF_HHI + SZ_BH)
#define OFF_WH   (OFF_HLO + SZ_BH)
#define SZ_W     ((size_t)24*512*512*2)
#define OFF_WL   (OFF_WH + SZ_W)
#define OFF_BQKV (OFF_WL + SZ_W)
#define SCRATCH_BYTES (OFF_BQKV + (size_t)LL*1536*4)

__device__ __align__(1024) unsigned char g_scratch[SCRATCH_BYTES];

// ---------------- helpers ----------------
__device__ __forceinline__ uint32_t smem_u32(const void* p) {
    uint32_t a;
    asm("{ .reg .u64 t; cvta.to.shared.u64 t, %1; cvt.u32.u64 %0, t; }" : "=r"(a) : "l"(p));
    return a;
}
__device__ __forceinline__ void cpa16(uint32_t dst, const void* src) {
    asm volatile("cp.async.cg.shared.global [%0], [%1], 16;" :: "r"(dst), "l"(src));
}
__device__ __forceinline__ void cpa_commit() {
    asm volatile("cp.async.commit_group;");
}
__device__ __forceinline__ void mma16816(float* c, uint32_t a0, uint32_t a1, uint32_t a2, uint32_t a3,
                                         uint32_t b0, uint32_t b1) {
    asm volatile(
        "mma.sync.aligned.m16n8k16.row.col.f32.bf16.bf16.f32 "
        "{%0,%1,%2,%3}, {%4,%5,%6,%7}, {%8,%9}, {%0,%1,%2,%3};"
        : "+f"(c[0]), "+f"(c[1]), "+f"(c[2]), "+f"(c[3])
        : "r"(a0), "r"(a1), "r"(a2), "r"(a3), "r"(b0), "r"(b1));
}
__device__ __forceinline__ void sp2(float a, float b, uint32_t& hu, uint32_t& lu) {
    __nv_bfloat16 ha = __float2bfloat16(a), hb = __float2bfloat16(b);
    __nv_bfloat16 la = __float2bfloat16(a - __bfloat162float(ha));
    __nv_bfloat16 lb = __float2bfloat16(b - __bfloat162float(hb));
    __nv_bfloat162 h2; h2.x = ha; h2.y = hb;
    __nv_bfloat162 l2; l2.x = la; l2.y = lb;
    hu = *reinterpret_cast<uint32_t*>(&h2);
    lu = *reinterpret_cast<uint32_t*>(&l2);
}

// ---------------- weight prep: Wt[m][n][k] = W_m[k][n], bf16 hi/lo ----------------
__global__ void prep_w(const float* __restrict__ Wq, const float* __restrict__ Wk,
                       const float* __restrict__ Wv, const float* __restrict__ Wo,
                       __nv_bfloat16* __restrict__ wh, __nv_bfloat16* __restrict__ wl) {
    __shared__ float tile[32][33];
    int m = blockIdx.z;
    int l = m >> 2, type = m & 3;
    const float* W = (type == 0 ? Wq : type == 1 ? Wk : type == 2 ? Wv : Wo) + (size_t)l * CC * CC;
    int k0 = blockIdx.x * 32, n0 = blockIdx.y * 32;
    int tx = threadIdx.x, ty = threadIdx.y;
    #pragma unroll
    for (int r = 0; r < 4; r++) {
        int k = ty + r * 8;
        tile[k][tx] = W[(size_t)(k0 + k) * CC + n0 + tx];
    }
    __syncthreads();
    #pragma unroll
    for (int r = 0; r < 4; r++) {
        int i = ty + r * 8;
        float v = tile[tx][i];
        size_t row = (size_t)m * 512 + n0 + i;
        __nv_bfloat16 h = __float2bfloat16(v);
        wh[row * 512 + k0 + tx] = h;
        wl[row * 512 + k0 + tx] = __float2bfloat16(v - __bfloat162float(h));
    }
}

__global__ void pack_b(const float* __restrict__ bq, const float* __restrict__ bk,
                       const float* __restrict__ bv, float* __restrict__ bqkv) {
    int idx = blockIdx.x * 1024 + threadIdx.x;
    if (idx >= LL * 1536) return;
    int l = idx / 1536, r = idx % 1536;
    bqkv[idx] = (r < 512) ? bq[l * 512 + r] : (r < 1024) ? bk[l * 512 + r - 512] : bv[l * 512 + r - 1024];
}

// ---------------- embedding (+ hi/lo split) ----------------
__global__ void embed_kernel(const int* __restrict__ tok, const float* __restrict__ wte,
                             const float* __restrict__ wpe, float* __restrict__ x,
                             __nv_bfloat16* __restrict__ xh, __nv_bfloat16* __restrict__ xl) {
    int row = blockIdx.x;
    int tid = threadIdx.x;
    int tkn = __ldg(tok + row);
    int t = row & (TT - 1);
    float4 a = ((const float4*)(wte + (size_t)tkn * CC))[tid];
    float4 p = ((const float4*)(wpe + (size_t)t * CC))[tid];
    float4 o;
    o.x = a.x + p.x; o.y = a.y + p.y; o.z = a.z + p.z; o.w = a.w + p.w;
    ((float4*)(x + (size_t)row * CC))[tid] = o;
    uint32_t h0, l0, h1, l1;
    sp2(o.x, o.y, h0, l0); sp2(o.z, o.w, h1, l1);
    ((uint2*)(xh + (size_t)row * CC))[tid] = make_uint2(h0, h1);
    ((uint2*)(xl + (size_t)row * CC))[tid] = make_uint2(l0, l1);
}

// ---------------- split-bf16 HMMA GEMM ----------------
// out[M, Ngemm](+bias)(+res) = A[M,512] @ Wt[n][k]^T, 3-pass hi/lo split.
// CTA tile 128x128, BK=32, 256 threads, 8 warps (2 m x 4 n), 64x32 per warp.
// smem: 2 stages x 4 tiles (Ah,Al,Wh,Wl) of [128][32] bf16, row stride 40 (pad).
#define TILE_W   2560          // words per tile (128*20)
#define STAGE_W  10240         // words per stage (4 tiles)
#define GEMM_SMEM (2*STAGE_W*4)

__global__ __launch_bounds__(256, 2)
void gemm_mma(const __nv_bfloat16* __restrict__ Ah, const __nv_bfloat16* __restrict__ Al,
              const __nv_bfloat16* __restrict__ Wh, const __nv_bfloat16* __restrict__ Wl,
              int w_row_base, const float* __restrict__ bias, const float* __restrict__ res,
              float* __restrict__ out, int ldout) {
    extern __shared__ uint32_t sw[];
    const int tid = threadIdx.x;
    const int lane = tid & 31;
    const int wid = tid >> 5;
    const int g = lane >> 2, tig = lane & 3;
    const int warp_m = wid & 1;          // 0..1 -> 64 rows each
    const int warp_n = wid >> 1;         // 0..3 -> 32 cols each
    const int mbase = blockIdx.y * 128;
    const int nb = blockIdx.x * 128;

    // --- loader setup: 2 chunks of 16B per tile per thread ---
    const int r0 = tid >> 2;             // 0..63
    const int c16 = tid & 3;             // 16B chunk in a 64B row
    const uint32_t sbase = smem_u32(sw);
    const uint32_t so0 = sbase + (uint32_t)(r0 * 80 + c16 * 16);
    const size_t arow0 = (size_t)(mbase + r0) * 512 + c16 * 8;
    const size_t wrow0 = (size_t)(w_row_base + nb + r0) * 512 + c16 * 8;

    float acc[4][4][4];
    #pragma unroll
    for (int i = 0; i < 4; i++)
        #pragma unroll
        for (int j = 0; j < 4; j++)
            #pragma unroll
            for (int q = 0; q < 4; q++) acc[i][j][q] = 0.f;

    auto issue = [&](int buf, int c) {
        const int k0 = c * 32;
        const uint32_t sb = so0 + (uint32_t)buf * (STAGE_W * 4);
        cpa16(sb,                      Ah + arow0 + k0);
        cpa16(sb + 5120,               Ah + arow0 + 64 * 512 + k0);
        cpa16(sb + TILE_W * 4,         Al + arow0 + k0);
        cpa16(sb + TILE_W * 4 + 5120,  Al + arow0 + 64 * 512 + k0);
        cpa16(sb + TILE_W * 8,         Wh + wrow0 + k0);
        cpa16(sb + TILE_W * 8 + 5120,  Wh + wrow0 + 64 * 512 + k0);
        cpa16(sb + TILE_W * 12,        Wl + wrow0 + k0);
        cpa16(sb + TILE_W * 12 + 5120, Wl + wrow0 + 64 * 512 + k0);
        cpa_commit();
    };

    issue(0, 0);
    issue(1, 1);

    #pragma unroll 1
    for (int c = 0; c < 16; c++) {
        if (c < 15) asm volatile("cp.async.wait_group 1;");
        else        asm volatile("cp.async.wait_group 0;");
        __syncthreads();

        const int wb = (c & 1) * STAGE_W;
        #pragma unroll
        for (int ks = 0; ks < 2; ks++) {
            const int kw = ks * 8 + tig;                 // word offset of a0 column pair
            uint32_t ah[4][4], al[4][4];
            #pragma unroll
            for (int mf = 0; mf < 4; mf++) {
                int r = warp_m * 64 + mf * 16 + g;
                int w0 = wb + r * 20 + kw;
                ah[mf][0] = sw[w0];
                ah[mf][1] = sw[w0 + 160];
                ah[mf][2] = sw[w0 + 4];
                ah[mf][3] = sw[w0 + 164];
                al[mf][0] = sw[w0 + TILE_W];
                al[mf][1] = sw[w0 + TILE_W + 160];
                al[mf][2] = sw[w0 + TILE_W + 4];
                al[mf][3] = sw[w0 + TILE_W + 164];
            }
            #pragma unroll
            for (int nf = 0; nf < 4; nf++) {
                int nr = warp_n * 32 + nf * 8 + g;
                int wB = wb + 2 * TILE_W + nr * 20 + kw;
                uint32_t bh0 = sw[wB],          bh1 = sw[wB + 4];
                uint32_t bl0 = sw[wB + TILE_W], bl1 = sw[wB + TILE_W + 4];
                #pragma unroll
                for (int mf = 0; mf < 4; mf++) {
                    mma16816(acc[mf][nf], ah[mf][0], ah[mf][1], ah[mf][2], ah[mf][3], bh0, bh1);
                    mma16816(acc[mf][nf], al[mf][0], al[mf][1], al[mf][2], al[mf][3], bh0, bh1);
                    mma16816(acc[mf][nf], ah[mf][0], ah[mf][1], ah[mf][2], ah[mf][3], bl0, bl1);
                }
            }
        }
        __syncthreads();
        if (c + 2 < 16) issue(c & 1, c + 2);
    }

    // --- epilogue: bias (+ residual), float2 stores ---
    #pragma unroll
    for (int nf = 0; nf < 4; nf++) {
        int col = nb + warp_n * 32 + nf * 8 + tig * 2;
        float2 b2 = *(const float2*)(bias + col);
        #pragma unroll
        for (int mf = 0; mf < 4; mf++) {
            int row = mbase + warp_m * 64 + mf * 16 + g;
            float2 o0, o1;
            o0.x = acc[mf][nf][0] + b2.x; o0.y = acc[mf][nf][1] + b2.y;
            o1.x = acc[mf][nf][2] + b2.x; o1.y = acc[mf][nf][3] + b2.y;
            if (res) {
                float2 r0v = *(const float2*)(res + (size_t)row * CC + col);
                float2 r1v = *(const float2*)(res + (size_t)(row + 8) * CC + col);
                o0.x += r0v.x; o0.y += r0v.y;
                o1.x += r1v.x; o1.y += r1v.y;
            }
            *(float2*)(out + (size_t)row * ldout + col) = o0;
            *(float2*)(out + (size_t)(row + 8) * ldout + col) = o1;
        }
    }
}

// ---------------- attention (per-position over heads), writes bf16 hi/lo ----------------
__global__ void attn_kernel(const float* __restrict__ qkv,
                            __nv_bfloat16* __restrict__ hh, __nv_bfloat16* __restrict__ hl) {
    int r = blockIdx.x;
    int t = threadIdx.x;                    // 0..63
    __shared__ float qs[512], ks[512], vs[512], att_s[64];

    const float4* bp = (const float4*)(qkv + (size_t)r * 1536);
    #pragma unroll
    for (int i = t; i < 128; i += 64) {
        ((float4*)qs)[i] = bp[i];
        ((float4*)ks)[i] = bp[128 + i];
        ((float4*)vs)[i] = bp[256 + i];
    }
    __syncthreads();

    int h = t >> 3, g = t & 7;
    float s = 0.f;
    #pragma unroll
    for (int d = 0; d < DD; d++) s += qs[h * DD + d] * ks[g * DD + d];
    s *= 0.125f;

    float m = s;
    #pragma unroll
    for (int o = 1; o < 8; o <<= 1) m = fmaxf(m, __shfl_xor_sync(0xffffffffu, m, o, 8));
    float e = expf(s - m);
    float sum = e;
    #pragma unroll
    for (int o = 1; o < 8; o <<= 1) sum += __shfl_xor_sync(0xffffffffu, sum, o, 8);
    att_s[t] = e / sum;
    __syncthreads();

    int j = t & 7;
    float accv[8] = {0.f, 0.f, 0.f, 0.f, 0.f, 0.f, 0.f, 0.f};
    #pragma unroll
    for (int g2 = 0; g2 < 8; g2++) {
        float a = att_s[h * 8 + g2];
        #pragma unroll
        for (int jj = 0; jj < 8; jj++)
            accv[jj] += a * vs[g2 * DD + j * 8 + jj];
    }
    uint32_t hu[4], lu[4];
    #pragma unroll
    for (int p = 0; p < 4; p++) sp2(accv[2 * p], accv[2 * p + 1], hu[p], lu[p]);
    size_t off = (size_t)r * CC + h * DD + j * 8;
    *(uint4*)(hh + off) = make_uint4(hu[0], hu[1], hu[2], hu[3]);
    *(uint4*)(hl + off) = make_uint4(lu[0], lu[1], lu[2], lu[3]);
}

// ---------------- LayerNorm (warp/row) with hi/lo split ----------------
__global__ void ln_kernel(const float* __restrict__ y, const float* __restrict__ g,
                          const float* __restrict__ b, float* __restrict__ xo,
                          __nv_bfloat16* __restrict__ xh, __nv_bfloat16* __restrict__ xl) {
    int warp = threadIdx.x >> 5;
    int lane = threadIdx.x & 31;
    size_t row = (size_t)blockIdx.x * 8 + warp;

    const float4* yp = (const float4*)(y + row * CC);
    float4 v[4];
    float s = 0.f, s2 = 0.f;
    #pragma unroll
    for (int i = 0; i < 4; i++) {
        v[i] = yp[lane + 32 * i];
        s  += v[i].x + v[i].y + v[i].z + v[i].w;
        s2 += v[i].x * v[i].x + v[i].y * v[i].y + v[i].z * v[i].z + v[i].w * v[i].w;
    }
    #pragma unroll
    for (int o = 16; o; o >>= 1) {
        s  += __shfl_xor_sync(0xffffffffu, s, o);
        s2 += __shfl_xor_sync(0xffffffffu, s2, o);
    }
    float mean = s * (1.f / 512.f);
    float var = s2 * (1.f / 512.f) - mean * mean;
    float rstd = rsqrtf(var + 1e-5f);

    float4* xp = (float4*)(xo + row * CC);
    uint2* hp = (uint2*)(xh + row * CC);
    uint2* lp = (uint2*)(xl + row * CC);
    const float4* gp = (const float4*)g;
    const float4* bp = (const float4*)b;
    #pragma unroll
    for (int i = 0; i < 4; i++) {
        float4 gg = gp[lane + 32 * i], bb = bp[lane + 32 * i], o;
        o.x = (v[i].x - mean) * rstd * gg.x + bb.x;
        o.y = (v[i].y - mean) * rstd * gg.y + bb.y;
        o.z = (v[i].z - mean) * rstd * gg.z + bb.z;
        o.w = (v[i].w - mean) * rstd * gg.w + bb.w;
        xp[lane + 32 * i] = o;
        uint32_t h0, l0, h1, l1;
        sp2(o.x, o.y, h0, l0); sp2(o.z, o.w, h1, l1);
        hp[lane + 32 * i] = make_uint2(h0, h1);
        lp[lane + 32 * i] = make_uint2(l0, l1);
    }
}

// ---------------- LM head + loss ----------------
__global__ void lmhead_kernel(const float* __restrict__ x, const float* __restrict__ Wlm,
                              const float* __restrict__ blm, float* __restrict__ logits) {
    int warp = threadIdx.x >> 5;
    int lane = threadIdx.x & 31;
    size_t row = (size_t)blockIdx.x * 8 + warp;

    float p[VV];
    #pragma unroll
    for (int vv = 0; vv < VV; vv++) p[vv] = 0.f;
    const float* xr = x + row * CC;
    for (int kk = lane; kk < CC; kk += 32) {
        float xv = xr[kk];
        const float* wrow = Wlm + (size_t)kk * VV;
        #pragma unroll
        for (int vv = 0; vv < VV; vv++) p[vv] += xv * wrow[vv];
    }
    #pragma unroll
    for (int vv = 0; vv < VV; vv++)
        #pragma unroll
        for (int o = 16; o; o >>= 1) p[vv] += __shfl_xor_sync(0xffffffffu, p[vv], o);
    if (lane == 0) {
        float* lp = logits + row * VV;
        #pragma unroll
        for (int vv = 0; vv < VV; vv++) lp[vv] = p[vv] + blm[vv];
    }
}

__global__ void loss_kernel(const float* __restrict__ logits, const int* __restrict__ label,
                            float* __restrict__ out_loss) {
    __shared__ float sdata[512];
    int b = threadIdx.x;
    const float* lg = logits + ((size_t)b * TT + (TT - 1)) * VV;
    float m = lg[0];
    #pragma unroll
    for (int vv = 1; vv < VV; vv++) m = fmaxf(m, lg[vv]);
    float s = 0.f;
    #pragma unroll
    for (int vv = 0; vv < VV; vv++) s += expf(lg[vv] - m);
    float lse = m + logf(s);
    sdata[b] = -(lg[label[b]] - lse);
    __syncthreads();
    for (int st = 256; st; st >>= 1) {
        if (b < st) sdata[b] += sdata[b + st];
        __syncthreads();
    }
    if (b == 0) *out_loss = sdata[0] * (1.f / BB);
}

// ---------------- host ----------------
extern "C" void kernel_launch(void* const* d_in, const int* in_sizes, int n_in,
                              void* d_out, int out_size) {
    const int*   tok   = (const int*)d_in[0];
    const int*   label = (const int*)d_in[1];
    const float* wte   = (const float*)d_in[2];
    const float* wpe   = (const float*)d_in[3];
    const float* Wq    = (const float*)d_in[4];
    const float* bq    = (const float*)d_in[5];
    const float* Wk    = (const float*)d_in[6];
    const float* bk    = (const float*)d_in[7];
    const float* Wv    = (const float*)d_in[8];
    const float* bv    = (const float*)d_in[9];
    const float* Wo    = (const float*)d_in[10];
    const float* bo    = (const float*)d_in[11];
    const float* ln_g  = (const float*)d_in[12];
    const float* ln_b  = (const float*)d_in[13];
    const float* Wlm   = (const float*)d_in[14];
    const float* blm   = (const float*)d_in[15];
    float* out = (float*)d_out;

    unsigned char* base = nullptr;
    cudaGetSymbolAddress((void**)&base, g_scratch);
    float* x    = (float*)(base + OFF_X);
    float* qkv  = (float*)(base + OFF_QKV);
    float* y    = (float*)(base + OFF_Y);
    __nv_bfloat16* xh = (__nv_bfloat16*)(base + OFF_XH);
    __nv_bfloat16* xl = (__nv_bfloat16*)(base + OFF_XL);
    __nv_bfloat16* hh = (__nv_bfloat16*)(base + OFF_HHI);
    __nv_bfloat16* hl = (__nv_bfloat16*)(base + OFF_HLO);
    __nv_bfloat16* wh = (__nv_bfloat16*)(base + OFF_WH);
    __nv_bfloat16* wl = (__nv_bfloat16*)(base + OFF_WL);
    float* bqkv = (float*)(base + OFF_BQKV);

    static bool attr_set = false;
    if (!attr_set) {
        cudaFuncSetAttribute(gemm_mma, cudaFuncAttributeMaxDynamicSharedMemorySize, GEMM_SMEM);
        attr_set = true;
    }

    prep_w<<<dim3(16, 16, 24), dim3(32, 8)>>>(Wq, Wk, Wv, Wo, wh, wl);
    pack_b<<<9, 1024>>>(bq, bk, bv, bqkv);

    embed_kernel<<<MM, 128>>>(tok, wte, wpe, x, xh, xl);

    for (int l = 0; l < LL; l++) {
        gemm_mma<<<dim3(12, MM / 128), 256, GEMM_SMEM>>>(xh, xl, wh, wl,
            l * 2048, bqkv + l * 1536, nullptr, qkv, 1536);
        attn_kernel<<<MM, 64>>>(qkv, hh, hl);
        gemm_mma<<<dim3(4, MM / 128), 256, GEMM_SMEM>>>(hh, hl, wh, wl,
            l * 2048 + 1536, bo + l * 512, x, y, 512);
        ln_kernel<<<MM / 8, 256>>>(y, ln_g + (size_t)l * CC, ln_b + (size_t)l * CC, x, xh, xl);
    }

    lmhead_kernel<<<MM / 8, 256>>>(x, Wlm, blm, out);
    if (out_size >= MM * VV + 1)
        loss_kernel<<<1, 512>>>(out, label, out + (MM * VV));
}